// round 3
// baseline (speedup 1.0000x reference)
#include <cuda_runtime.h>

// BatchDotPred: out[e] = dot(feat[src[e]], feat[dst[e]]), D=128.
//
// Strategy: the feat table (51MB) is L2-resident, and R1 showed we are pinned
// at the LTS (~6300 B/cyc) cap moving 2.07GB/launch. Reduce L2 bytes:
// bucket edges by src into node-range buckets; one block per bucket stages its
// src rows in SMEM (feat read exactly once = 51MB), so only dst gathers
// (1.02GB) hit L2. ~1.2GB total vs 2.07GB.

#define NBK 2048            // buckets
#define MAX_ROWS 49         // ceil(100000/2048)
#define MAX_EDGES 2000000

// Scratch (device globals — no allocation allowed)
__device__ int  g_count[NBK];
__device__ int  g_cursor[NBK];
__device__ int  g_offset[NBK];
__device__ int2 g_esorted[MAX_EDGES];
__device__ int  g_eidx[MAX_EDGES];

static __device__ __forceinline__ int bucket_of(int node, int n_nodes) {
    return (int)(((long long)node * NBK) / n_nodes);
}

__global__ void zero_k() {
    int i = blockIdx.x * blockDim.x + threadIdx.x;
    if (i < NBK) { g_count[i] = 0; g_cursor[i] = 0; }
}

__global__ void hist_k(const int2* __restrict__ edges, int n, int n_nodes) {
    int i = blockIdx.x * blockDim.x + threadIdx.x;
    if (i < n) {
        int b = bucket_of(edges[i].x, n_nodes);
        atomicAdd(&g_count[b], 1);
    }
}

// Exclusive scan of g_count[0..NBK) into g_offset. One block, 1024 threads,
// each thread owns 2 buckets; Hillis-Steele over the 1024 pair-sums.
__global__ void scan_k() {
    __shared__ int p[1024];
    int t = threadIdx.x;
    int c0 = g_count[2 * t];
    int c1 = g_count[2 * t + 1];
    p[t] = c0 + c1;
    __syncthreads();
    #pragma unroll
    for (int d = 1; d < 1024; d <<= 1) {
        int v = p[t];
        int add = (t >= d) ? p[t - d] : 0;
        __syncthreads();
        p[t] = v + add;
        __syncthreads();
    }
    int excl = (t == 0) ? 0 : p[t - 1];
    g_offset[2 * t]     = excl;
    g_offset[2 * t + 1] = excl + c0;
}

__global__ void scatter_k(const int2* __restrict__ edges, int n, int n_nodes) {
    int i = blockIdx.x * blockDim.x + threadIdx.x;
    if (i < n) {
        int2 e = edges[i];
        int b = bucket_of(e.x, n_nodes);
        int pos = g_offset[b] + atomicAdd(&g_cursor[b], 1);
        g_esorted[pos] = e;
        g_eidx[pos]    = i;
    }
}

// One block per bucket. 256 threads = 8 warps; warp-per-edge, 2-edge ILP.
__global__ void __launch_bounds__(256) dot_bucket_k(
    const float4* __restrict__ feat, float* __restrict__ out, int n_nodes)
{
    int b  = blockIdx.x;
    int lo = (int)(((long long)b       * n_nodes + NBK - 1) / NBK);
    int hi = (int)(((long long)(b + 1) * n_nodes + NBK - 1) / NBK);
    if (hi > n_nodes) hi = n_nodes;
    int nrows = hi - lo;

    __shared__ float4 srows[MAX_ROWS * 32];   // 49 rows * 512B = 25088B

    for (int i = threadIdx.x; i < nrows * 32; i += 256)
        srows[i] = feat[(size_t)lo * 32 + i];
    __syncthreads();

    int start = g_offset[b];
    int cnt   = g_count[b];
    int warp  = threadIdx.x >> 5;
    int lane  = threadIdx.x & 31;

    for (int i = warp; i < cnt; i += 16) {
        int j = i + 8;
        bool hasj = (j < cnt);

        int2 e0 = g_esorted[start + i];
        int2 e1 = hasj ? g_esorted[start + j] : e0;

        // issue both dst gathers before any reduction work
        float4 d0 = __ldg(&feat[(size_t)e0.y * 32 + lane]);
        float4 d1 = __ldg(&feat[(size_t)e1.y * 32 + lane]);

        float4 a0 = srows[(e0.x - lo) * 32 + lane];
        float4 a1 = srows[(e1.x - lo) * 32 + lane];

        float s0 = a0.x * d0.x + a0.y * d0.y + a0.z * d0.z + a0.w * d0.w;
        float s1 = a1.x * d1.x + a1.y * d1.y + a1.z * d1.z + a1.w * d1.w;

        #pragma unroll
        for (int o = 16; o > 0; o >>= 1) {
            s0 += __shfl_xor_sync(0xffffffffu, s0, o);
            s1 += __shfl_xor_sync(0xffffffffu, s1, o);
        }

        if (lane == 0) {
            out[g_eidx[start + i]] = s0;
            if (hasj) out[g_eidx[start + j]] = s1;
        }
    }
}

extern "C" void kernel_launch(void* const* d_in, const int* in_sizes, int n_in,
                              void* d_out, int out_size)
{
    const int2*   edges = (const int2*)d_in[0];
    const float4* feat  = (const float4*)d_in[1];
    float*        out   = (float*)d_out;

    int n_edges = in_sizes[0] / 2;
    int n_nodes = in_sizes[1] / 128;

    int eb = (n_edges + 255) / 256;

    zero_k<<<(NBK + 255) / 256, 256>>>();
    hist_k<<<eb, 256>>>(edges, n_edges, n_nodes);
    scan_k<<<1, 1024>>>();
    scatter_k<<<eb, 256>>>(edges, n_edges, n_nodes);
    dot_bucket_k<<<NBK, 256>>>(feat, out, n_nodes);
}

// round 7
// speedup vs baseline: 2.5322x; 2.5322x over previous
#include <cuda_runtime.h>
#include <cuda_fp16.h>

// BatchDotPred: out[e] = dot(feat[src[e]], feat[dst[e]]), D=128.
//
// R1 showed the kernel is pinned at the L2/LTS byte cap (~6300 B/cyc) moving
// 2.07GB. R2 (reorder) lost to atomic/scatter overhead. R3/R6: halve gathered
// bytes with an fp16 mirror of feat (built in-launch, ~8us), accumulate fp32.
// Norm rel_err predicted ~4e-4 < 1e-3.

#define N_NODES_MAX 100000

// fp16 feature table: 100000 rows x 128 halves = 256B/row, as uint4 (8 halves).
__device__ uint4 g_featH[N_NODES_MAX * 16];

// Convert: thread i handles 8 floats (two float4) -> one uint4 of 8 halves.
__global__ void __launch_bounds__(256) convert_k(const float4* __restrict__ feat, int n8)
{
    int i = blockIdx.x * blockDim.x + threadIdx.x;   // i in [0, N*16)
    if (i >= n8) return;
    float4 a = feat[2 * i];
    float4 b = feat[2 * i + 1];
    __half2 h0 = __floats2half2_rn(a.x, a.y);
    __half2 h1 = __floats2half2_rn(a.z, a.w);
    __half2 h2 = __floats2half2_rn(b.x, b.y);
    __half2 h3 = __floats2half2_rn(b.z, b.w);
    uint4 v;
    v.x = *reinterpret_cast<unsigned int*>(&h0);
    v.y = *reinterpret_cast<unsigned int*>(&h1);
    v.z = *reinterpret_cast<unsigned int*>(&h2);
    v.w = *reinterpret_cast<unsigned int*>(&h3);
    g_featH[i] = v;
}

// Dot: one half-warp (16 lanes) per edge. Each lane loads one uint4 (8 halves)
// from each row -> 256B coalesced per half-warp per row. fp32 accumulate.
__global__ void __launch_bounds__(256) batch_dot_h_kernel(
    const int2* __restrict__ edges,
    float* __restrict__ out,
    int n_edges)
{
    int gtid = blockIdx.x * blockDim.x + threadIdx.x;
    int e    = gtid >> 4;          // half-warp index = edge index
    int lane = gtid & 15;
    if (e >= n_edges) return;

    int2 ed = edges[e];            // broadcast within half-warp

    uint4 sa = __ldg(&g_featH[(size_t)ed.x * 16 + lane]);
    uint4 sb = __ldg(&g_featH[(size_t)ed.y * 16 + lane]);

    const __half2* ha = reinterpret_cast<const __half2*>(&sa);
    const __half2* hb = reinterpret_cast<const __half2*>(&sb);

    float s = 0.0f;
    #pragma unroll
    for (int k = 0; k < 4; k++) {
        float2 fa = __half22float2(ha[k]);
        float2 fb = __half22float2(hb[k]);
        s = fmaf(fa.x, fb.x, s);
        s = fmaf(fa.y, fb.y, s);
    }

    // reduce across the 16-lane group (xor offsets stay inside the group)
    #pragma unroll
    for (int off = 8; off > 0; off >>= 1)
        s += __shfl_xor_sync(0xffffffffu, s, off);

    if (lane == 0) out[e] = s;
}

extern "C" void kernel_launch(void* const* d_in, const int* in_sizes, int n_in,
                              void* d_out, int out_size)
{
    const int2*   edges = (const int2*)d_in[0];
    const float4* feat  = (const float4*)d_in[1];
    float*        out   = (float*)d_out;

    int n_edges = in_sizes[0] / 2;
    int n_nodes = in_sizes[1] / 128;
    int n8      = n_nodes * 16;            // uint4 count in fp16 table

    convert_k<<<(n8 + 255) / 256, 256>>>(feat, n8);

    long long total_threads = (long long)n_edges * 16;
    int blocks = (int)((total_threads + 255) / 256);
    batch_dot_h_kernel<<<blocks, 256>>>(edges, out, n_edges);
}

// round 11
// speedup vs baseline: 3.6393x; 1.4372x over previous
#include <cuda_runtime.h>
#include <cuda_fp16.h>

// BatchDotPred: out[e] = dot(feat[src[e]], feat[dst[e]]), D=128.
//
// R6: fp16 mirror halved L2 bytes -> 168us, but dot kernel became
// issue/instruction-bound (16 F2F converts per lane dominated).
// R7/R10: half2 HMUL2/HFMA2 chains cut per-lane math 24 -> 11 instrs.
// (R9 bench was an infra failure; resubmitting the same candidate.)
// Predicted rel_err ~4-5e-4 (fp16 partial sums limited to 2-term chains).

#define N_NODES_MAX 100000

// fp16 feature table: 100000 rows x 128 halves = 256B/row, as uint4 (8 halves).
__device__ uint4 g_featH[N_NODES_MAX * 16];

// Convert: thread i handles 8 floats (two float4) -> one uint4 of 8 halves.
__global__ void __launch_bounds__(256) convert_k(const float4* __restrict__ feat, int n8)
{
    int i = blockIdx.x * blockDim.x + threadIdx.x;   // i in [0, N*16)
    if (i >= n8) return;
    float4 a = feat[2 * i];
    float4 b = feat[2 * i + 1];
    __half2 h0 = __floats2half2_rn(a.x, a.y);
    __half2 h1 = __floats2half2_rn(a.z, a.w);
    __half2 h2 = __floats2half2_rn(b.x, b.y);
    __half2 h3 = __floats2half2_rn(b.z, b.w);
    uint4 v;
    v.x = *reinterpret_cast<unsigned int*>(&h0);
    v.y = *reinterpret_cast<unsigned int*>(&h1);
    v.z = *reinterpret_cast<unsigned int*>(&h2);
    v.w = *reinterpret_cast<unsigned int*>(&h3);
    g_featH[i] = v;
}

// Dot: one half-warp (16 lanes) per edge. Each lane loads one uint4 (8 halves)
// from each row -> 256B coalesced per half-warp per row.
// Math: two independent half2 chains (2 terms each) then fp32 finish.
__global__ void __launch_bounds__(256) batch_dot_h_kernel(
    const int2* __restrict__ edges,
    float* __restrict__ out,
    int n_edges)
{
    int gtid = blockIdx.x * blockDim.x + threadIdx.x;
    int e    = gtid >> 4;          // 16-lane group index = edge index
    int lane = gtid & 15;
    if (e >= n_edges) return;

    int2 ed = edges[e];            // broadcast within group

    uint4 sa = __ldg(&g_featH[(size_t)ed.x * 16 + lane]);
    uint4 sb = __ldg(&g_featH[(size_t)ed.y * 16 + lane]);

    const __half2* ha = reinterpret_cast<const __half2*>(&sa);
    const __half2* hb = reinterpret_cast<const __half2*>(&sb);

    // Two independent fp16 chains, each SIMD slot accumulates only 2 products
    // (keeps fp16 rounding error small), then convert once and finish in fp32.
    __half2 cA = __hmul2(ha[0], hb[0]);
    __half2 cB = __hmul2(ha[1], hb[1]);
    cA = __hfma2(ha[2], hb[2], cA);
    cB = __hfma2(ha[3], hb[3], cB);

    float2 fA = __half22float2(cA);
    float2 fB = __half22float2(cB);
    float s = (fA.x + fA.y) + (fB.x + fB.y);

    // reduce across the 16-lane group (xor offsets stay inside the group)
    #pragma unroll
    for (int off = 8; off > 0; off >>= 1)
        s += __shfl_xor_sync(0xffffffffu, s, off);

    if (lane == 0) out[e] = s;
}

extern "C" void kernel_launch(void* const* d_in, const int* in_sizes, int n_in,
                              void* d_out, int out_size)
{
    const int2*   edges = (const int2*)d_in[0];
    const float4* feat  = (const float4*)d_in[1];
    float*        out   = (float*)d_out;

    int n_edges = in_sizes[0] / 2;
    int n_nodes = in_sizes[1] / 128;
    int n8      = n_nodes * 16;            // uint4 count in fp16 table

    convert_k<<<(n8 + 255) / 256, 256>>>(feat, n8);

    long long total_threads = (long long)n_edges * 16;
    int blocks = (int)((total_threads + 255) / 256);
    batch_dot_h_kernel<<<blocks, 256>>>(edges, out, n_edges);
}

// round 12
// speedup vs baseline: 5.1735x; 1.4216x over previous
#include <cuda_runtime.h>
#include <cuda_fp16.h>

// BatchDotPred: out[e] = dot(feat[src[e]], feat[dst[e]]), D=128.
//
// R6: fp16 mirror halved L2 bytes. R10: half2 math -> 117us, rel_err 3.9e-4.
// LTS byte floor for 1.05GB is ~95us; R10 dot kernel at 112.8us (1.19x floor)
// with issue/L1 pipes unsaturated -> latency-overlap residual.
// R11: 2 edges per 16-lane group (4 gathers in flight/lane), fused int4 edge
// load, fused float2 output store.

#define N_NODES_MAX 100000

// fp16 feature table: 100000 rows x 128 halves = 256B/row, as uint4 (8 halves).
__device__ uint4 g_featH[N_NODES_MAX * 16];

__global__ void __launch_bounds__(256) convert_k(const float4* __restrict__ feat, int n8)
{
    int i = blockIdx.x * blockDim.x + threadIdx.x;   // i in [0, N*16)
    if (i >= n8) return;
    float4 a = feat[2 * i];
    float4 b = feat[2 * i + 1];
    __half2 h0 = __floats2half2_rn(a.x, a.y);
    __half2 h1 = __floats2half2_rn(a.z, a.w);
    __half2 h2 = __floats2half2_rn(b.x, b.y);
    __half2 h3 = __floats2half2_rn(b.z, b.w);
    uint4 v;
    v.x = *reinterpret_cast<unsigned int*>(&h0);
    v.y = *reinterpret_cast<unsigned int*>(&h1);
    v.z = *reinterpret_cast<unsigned int*>(&h2);
    v.w = *reinterpret_cast<unsigned int*>(&h3);
    g_featH[i] = v;
}

static __device__ __forceinline__ float dot8(uint4 sa, uint4 sb)
{
    const __half2* ha = reinterpret_cast<const __half2*>(&sa);
    const __half2* hb = reinterpret_cast<const __half2*>(&sb);
    __half2 cA = __hmul2(ha[0], hb[0]);
    __half2 cB = __hmul2(ha[1], hb[1]);
    cA = __hfma2(ha[2], hb[2], cA);
    cB = __hfma2(ha[3], hb[3], cB);
    float2 fA = __half22float2(cA);
    float2 fB = __half22float2(cB);
    return (fA.x + fA.y) + (fB.x + fB.y);
}

// One 16-lane group handles TWO consecutive edges (4 row gathers in flight).
__global__ void __launch_bounds__(256) batch_dot_h2_kernel(
    const int4* __restrict__ edges2,   // pairs of edges: (s0,d0,s1,d1)
    float2* __restrict__ out2,         // pairs of outputs
    int n_groups)                      // = n_edges/2 (n_edges even)
{
    int gtid = blockIdx.x * blockDim.x + threadIdx.x;
    int g    = gtid >> 4;          // group index = edge-pair index
    int lane = gtid & 15;
    if (g >= n_groups) return;

    int4 ed = edges2[g];           // broadcast within group: e0=(x,y) e1=(z,w)

    // issue all four gathers before any math
    uint4 sa0 = __ldg(&g_featH[(size_t)ed.x * 16 + lane]);
    uint4 sb0 = __ldg(&g_featH[(size_t)ed.y * 16 + lane]);
    uint4 sa1 = __ldg(&g_featH[(size_t)ed.z * 16 + lane]);
    uint4 sb1 = __ldg(&g_featH[(size_t)ed.w * 16 + lane]);

    float s0 = dot8(sa0, sb0);
    float s1 = dot8(sa1, sb1);

    // interleaved reductions across the 16-lane group
    #pragma unroll
    for (int off = 8; off > 0; off >>= 1) {
        s0 += __shfl_xor_sync(0xffffffffu, s0, off);
        s1 += __shfl_xor_sync(0xffffffffu, s1, off);
    }

    if (lane == 0) out2[g] = make_float2(s0, s1);
}

// Scalar tail (only used if n_edges is odd).
__global__ void batch_dot_tail_kernel(
    const int2* __restrict__ edges, float* __restrict__ out, int e)
{
    int lane = threadIdx.x;        // 16 threads
    int2 ed = edges[e];
    uint4 sa = __ldg(&g_featH[(size_t)ed.x * 16 + lane]);
    uint4 sb = __ldg(&g_featH[(size_t)ed.y * 16 + lane]);
    float s = dot8(sa, sb);
    #pragma unroll
    for (int off = 8; off > 0; off >>= 1)
        s += __shfl_xor_sync(0xffffffffu, s, off);
    if (lane == 0) out[e] = s;
}

extern "C" void kernel_launch(void* const* d_in, const int* in_sizes, int n_in,
                              void* d_out, int out_size)
{
    const int2* edges = (const int2*)d_in[0];
    const float4* feat = (const float4*)d_in[1];
    float* out = (float*)d_out;

    int n_edges = in_sizes[0] / 2;
    int n_nodes = in_sizes[1] / 128;
    int n8      = n_nodes * 16;

    convert_k<<<(n8 + 255) / 256, 256>>>(feat, n8);

    int n_groups = n_edges / 2;
    long long total_threads = (long long)n_groups * 16;
    int blocks = (int)((total_threads + 255) / 256);
    batch_dot_h2_kernel<<<blocks, 256>>>((const int4*)edges, (float2*)out, n_groups);

    if (n_edges & 1)
        batch_dot_tail_kernel<<<1, 16>>>(edges, out, n_edges - 1);
}

// round 14
// speedup vs baseline: 5.9074x; 1.1418x over previous
#include <cuda_runtime.h>
#include <cuda_fp16.h>

// BatchDotPred: out[e] = dot(feat[src[e]], feat[dst[e]]), D=128.
//
// R6: fp16 mirror halved gather bytes. R10: half2 math. R11: 2-edge ILP
// -> 82.4us (dot 74.75us, L1tex 69.9% = top pipe).
// R12: 4 edges per 16-lane group (8 row gathers in flight per lane) to
// saturate L1tex; float4 fused output store.

#define N_NODES_MAX 100000

// fp16 feature table: 100000 rows x 128 halves = 256B/row, as uint4 (8 halves).
__device__ uint4 g_featH[N_NODES_MAX * 16];

__global__ void __launch_bounds__(256) convert_k(const float4* __restrict__ feat, int n8)
{
    int i = blockIdx.x * blockDim.x + threadIdx.x;   // i in [0, N*16)
    if (i >= n8) return;
    float4 a = feat[2 * i];
    float4 b = feat[2 * i + 1];
    __half2 h0 = __floats2half2_rn(a.x, a.y);
    __half2 h1 = __floats2half2_rn(a.z, a.w);
    __half2 h2 = __floats2half2_rn(b.x, b.y);
    __half2 h3 = __floats2half2_rn(b.z, b.w);
    uint4 v;
    v.x = *reinterpret_cast<unsigned int*>(&h0);
    v.y = *reinterpret_cast<unsigned int*>(&h1);
    v.z = *reinterpret_cast<unsigned int*>(&h2);
    v.w = *reinterpret_cast<unsigned int*>(&h3);
    g_featH[i] = v;
}

static __device__ __forceinline__ float dot8(uint4 sa, uint4 sb)
{
    const __half2* ha = reinterpret_cast<const __half2*>(&sa);
    const __half2* hb = reinterpret_cast<const __half2*>(&sb);
    __half2 cA = __hmul2(ha[0], hb[0]);
    __half2 cB = __hmul2(ha[1], hb[1]);
    cA = __hfma2(ha[2], hb[2], cA);
    cB = __hfma2(ha[3], hb[3], cB);
    float2 fA = __half22float2(cA);
    float2 fB = __half22float2(cB);
    return (fA.x + fA.y) + (fB.x + fB.y);
}

// One 16-lane group handles FOUR consecutive edges (8 row gathers in flight).
__global__ void __launch_bounds__(256) batch_dot_h4_kernel(
    const int4* __restrict__ edges2,   // edge pairs: (s,d,s,d)
    float4* __restrict__ out4,         // quads of outputs
    int n_groups)                      // = n_edges/4
{
    int gtid = blockIdx.x * blockDim.x + threadIdx.x;
    int g    = gtid >> 4;          // group index = edge-quad index
    int lane = gtid & 15;
    if (g >= n_groups) return;

    int4 ea = edges2[2 * g];       // edges 4g, 4g+1
    int4 eb = edges2[2 * g + 1];   // edges 4g+2, 4g+3

    // issue all eight gathers before any math
    uint4 sa0 = __ldg(&g_featH[(size_t)ea.x * 16 + lane]);
    uint4 sb0 = __ldg(&g_featH[(size_t)ea.y * 16 + lane]);
    uint4 sa1 = __ldg(&g_featH[(size_t)ea.z * 16 + lane]);
    uint4 sb1 = __ldg(&g_featH[(size_t)ea.w * 16 + lane]);
    uint4 sa2 = __ldg(&g_featH[(size_t)eb.x * 16 + lane]);
    uint4 sb2 = __ldg(&g_featH[(size_t)eb.y * 16 + lane]);
    uint4 sa3 = __ldg(&g_featH[(size_t)eb.z * 16 + lane]);
    uint4 sb3 = __ldg(&g_featH[(size_t)eb.w * 16 + lane]);

    float s0 = dot8(sa0, sb0);
    float s1 = dot8(sa1, sb1);
    float s2 = dot8(sa2, sb2);
    float s3 = dot8(sa3, sb3);

    // interleaved reductions across the 16-lane group
    #pragma unroll
    for (int off = 8; off > 0; off >>= 1) {
        s0 += __shfl_xor_sync(0xffffffffu, s0, off);
        s1 += __shfl_xor_sync(0xffffffffu, s1, off);
        s2 += __shfl_xor_sync(0xffffffffu, s2, off);
        s3 += __shfl_xor_sync(0xffffffffu, s3, off);
    }

    if (lane == 0) out4[g] = make_float4(s0, s1, s2, s3);
}

// Tail: one 16-lane group per remaining edge (n_edges % 4 edges).
__global__ void batch_dot_tail_kernel(
    const int2* __restrict__ edges, float* __restrict__ out,
    int e_start, int n_edges)
{
    int e    = e_start + (threadIdx.x >> 4);
    int lane = threadIdx.x & 15;
    if (e >= n_edges) return;
    int2 ed = edges[e];
    uint4 sa = __ldg(&g_featH[(size_t)ed.x * 16 + lane]);
    uint4 sb = __ldg(&g_featH[(size_t)ed.y * 16 + lane]);
    float s = dot8(sa, sb);
    #pragma unroll
    for (int off = 8; off > 0; off >>= 1)
        s += __shfl_xor_sync(0xffffffffu, s, off);
    if (lane == 0) out[e] = s;
}

extern "C" void kernel_launch(void* const* d_in, const int* in_sizes, int n_in,
                              void* d_out, int out_size)
{
    const int2* edges = (const int2*)d_in[0];
    const float4* feat = (const float4*)d_in[1];
    float* out = (float*)d_out;

    int n_edges = in_sizes[0] / 2;
    int n_nodes = in_sizes[1] / 128;
    int n8      = n_nodes * 16;

    convert_k<<<(n8 + 255) / 256, 256>>>(feat, n8);

    int n_groups = n_edges / 4;
    long long total_threads = (long long)n_groups * 16;
    int blocks = (int)((total_threads + 255) / 256);
    if (blocks > 0)
        batch_dot_h4_kernel<<<blocks, 256>>>((const int4*)edges, (float4*)out, n_groups);

    int tail = n_edges - n_groups * 4;
    if (tail > 0)
        batch_dot_tail_kernel<<<1, 16 * tail>>>(edges, out, n_groups * 4, n_edges);
}

// round 15
// speedup vs baseline: 6.0826x; 1.0297x over previous
#include <cuda_runtime.h>
#include <cuda_fp16.h>

// BatchDotPred: out[e] = dot(feat[src[e]], feat[dst[e]]), D=128.
//
// R6: fp16 mirror halved gather bytes. R10: half2 math. R11/R12: 2->4 edge
// ILP -> 72.2us (dot 64.2us, L1tex 79.8% top pipe, issue 49%).
// R13: 8 edges per 16-lane group (16 row gathers in flight per lane) to close
// the remaining latency-exposure gap toward the ~51us L1 wavefront floor.

#define N_NODES_MAX 100000

// fp16 feature table: 100000 rows x 128 halves = 256B/row, as uint4 (8 halves).
__device__ uint4 g_featH[N_NODES_MAX * 16];

__global__ void __launch_bounds__(256) convert_k(const float4* __restrict__ feat, int n8)
{
    int i = blockIdx.x * blockDim.x + threadIdx.x;   // i in [0, N*16)
    if (i >= n8) return;
    float4 a = feat[2 * i];
    float4 b = feat[2 * i + 1];
    __half2 h0 = __floats2half2_rn(a.x, a.y);
    __half2 h1 = __floats2half2_rn(a.z, a.w);
    __half2 h2 = __floats2half2_rn(b.x, b.y);
    __half2 h3 = __floats2half2_rn(b.z, b.w);
    uint4 v;
    v.x = *reinterpret_cast<unsigned int*>(&h0);
    v.y = *reinterpret_cast<unsigned int*>(&h1);
    v.z = *reinterpret_cast<unsigned int*>(&h2);
    v.w = *reinterpret_cast<unsigned int*>(&h3);
    g_featH[i] = v;
}

static __device__ __forceinline__ float dot8(uint4 sa, uint4 sb)
{
    const __half2* ha = reinterpret_cast<const __half2*>(&sa);
    const __half2* hb = reinterpret_cast<const __half2*>(&sb);
    __half2 cA = __hmul2(ha[0], hb[0]);
    __half2 cB = __hmul2(ha[1], hb[1]);
    cA = __hfma2(ha[2], hb[2], cA);
    cB = __hfma2(ha[3], hb[3], cB);
    float2 fA = __half22float2(cA);
    float2 fB = __half22float2(cB);
    return (fA.x + fA.y) + (fB.x + fB.y);
}

// One 16-lane group handles EIGHT consecutive edges (16 row gathers in flight).
__global__ void __launch_bounds__(256) batch_dot_h8_kernel(
    const int4* __restrict__ edges2,   // edge pairs: (s,d,s,d)
    float4* __restrict__ out4,         // output quads
    int n_groups)                      // = n_edges/8
{
    int gtid = blockIdx.x * blockDim.x + threadIdx.x;
    int g    = gtid >> 4;          // group index = 8-edge chunk
    int lane = gtid & 15;
    if (g >= n_groups) return;

    int4 ea = edges2[4 * g];       // edges 8g+0, 8g+1
    int4 eb = edges2[4 * g + 1];   // edges 8g+2, 8g+3
    int4 ec = edges2[4 * g + 2];   // edges 8g+4, 8g+5
    int4 ed = edges2[4 * g + 3];   // edges 8g+6, 8g+7

    // issue all sixteen gathers before any math
    uint4 sa0 = __ldg(&g_featH[(size_t)ea.x * 16 + lane]);
    uint4 sb0 = __ldg(&g_featH[(size_t)ea.y * 16 + lane]);
    uint4 sa1 = __ldg(&g_featH[(size_t)ea.z * 16 + lane]);
    uint4 sb1 = __ldg(&g_featH[(size_t)ea.w * 16 + lane]);
    uint4 sa2 = __ldg(&g_featH[(size_t)eb.x * 16 + lane]);
    uint4 sb2 = __ldg(&g_featH[(size_t)eb.y * 16 + lane]);
    uint4 sa3 = __ldg(&g_featH[(size_t)eb.z * 16 + lane]);
    uint4 sb3 = __ldg(&g_featH[(size_t)eb.w * 16 + lane]);
    uint4 sa4 = __ldg(&g_featH[(size_t)ec.x * 16 + lane]);
    uint4 sb4 = __ldg(&g_featH[(size_t)ec.y * 16 + lane]);
    uint4 sa5 = __ldg(&g_featH[(size_t)ec.z * 16 + lane]);
    uint4 sb5 = __ldg(&g_featH[(size_t)ec.w * 16 + lane]);
    uint4 sa6 = __ldg(&g_featH[(size_t)ed.x * 16 + lane]);
    uint4 sb6 = __ldg(&g_featH[(size_t)ed.y * 16 + lane]);
    uint4 sa7 = __ldg(&g_featH[(size_t)ed.z * 16 + lane]);
    uint4 sb7 = __ldg(&g_featH[(size_t)ed.w * 16 + lane]);

    float s0 = dot8(sa0, sb0);
    float s1 = dot8(sa1, sb1);
    float s2 = dot8(sa2, sb2);
    float s3 = dot8(sa3, sb3);
    float s4 = dot8(sa4, sb4);
    float s5 = dot8(sa5, sb5);
    float s6 = dot8(sa6, sb6);
    float s7 = dot8(sa7, sb7);

    // interleaved reductions across the 16-lane group
    #pragma unroll
    for (int off = 8; off > 0; off >>= 1) {
        s0 += __shfl_xor_sync(0xffffffffu, s0, off);
        s1 += __shfl_xor_sync(0xffffffffu, s1, off);
        s2 += __shfl_xor_sync(0xffffffffu, s2, off);
        s3 += __shfl_xor_sync(0xffffffffu, s3, off);
        s4 += __shfl_xor_sync(0xffffffffu, s4, off);
        s5 += __shfl_xor_sync(0xffffffffu, s5, off);
        s6 += __shfl_xor_sync(0xffffffffu, s6, off);
        s7 += __shfl_xor_sync(0xffffffffu, s7, off);
    }

    if (lane == 0) {
        out4[2 * g]     = make_float4(s0, s1, s2, s3);
        out4[2 * g + 1] = make_float4(s4, s5, s6, s7);
    }
}

// Tail: one 16-lane group per remaining edge (n_edges % 8 edges).
__global__ void batch_dot_tail_kernel(
    const int2* __restrict__ edges, float* __restrict__ out,
    int e_start, int n_edges)
{
    int e    = e_start + (threadIdx.x >> 4);
    int lane = threadIdx.x & 15;
    if (e >= n_edges) return;
    int2 ed = edges[e];
    uint4 sa = __ldg(&g_featH[(size_t)ed.x * 16 + lane]);
    uint4 sb = __ldg(&g_featH[(size_t)ed.y * 16 + lane]);
    float s = dot8(sa, sb);
    #pragma unroll
    for (int off = 8; off > 0; off >>= 1)
        s += __shfl_xor_sync(0xffffffffu, s, off);
    if (lane == 0) out[e] = s;
}

extern "C" void kernel_launch(void* const* d_in, const int* in_sizes, int n_in,
                              void* d_out, int out_size)
{
    const int2* edges = (const int2*)d_in[0];
    const float4* feat = (const float4*)d_in[1];
    float* out = (float*)d_out;

    int n_edges = in_sizes[0] / 2;
    int n_nodes = in_sizes[1] / 128;
    int n8      = n_nodes * 16;

    convert_k<<<(n8 + 255) / 256, 256>>>(feat, n8);

    int n_groups = n_edges / 8;
    long long total_threads = (long long)n_groups * 16;
    int blocks = (int)((total_threads + 255) / 256);
    if (blocks > 0)
        batch_dot_h8_kernel<<<blocks, 256>>>((const int4*)edges, (float4*)out, n_groups);

    int tail = n_edges - n_groups * 8;
    if (tail > 0)
        batch_dot_tail_kernel<<<1, 16 * tail>>>(edges, out, n_groups * 8, n_edges);
}